// round 6
// baseline (speedup 1.0000x reference)
#include <cuda_runtime.h>
#include <cuda_bf16.h>

// ============================================================================
// 2-layer LSTM language model, B=32, S=512, E=H=1024, V=32000.
//
//   prep:  weights fp32 -> bf16 transposed+permuted; embedding gather -> bf16;
//          zero h[0]; reset counters (runs every graph replay).
//   main:  persistent kernel, 128 CTAs (64 per layer), pipelined via monotone
//          counters. Per CTA per step: 64x32x2048 bf16 mma.sync GEMM + LSTM
//          cell for 16 hidden units; c-state in registers.
//   tail:  FC -> logits into d_out, then in-place softmax.
// ============================================================================

#define B_     32
#define S_     512
#define H_     1024
#define V_     32000
#define KTOT   2048
#define GPL    64            // CTAs per layer
#define KCHUNK 128
#define NCHUNK (KTOT / KCHUNK)   // 16
#define BSTRIDE 2056         // smem B row stride in halves (4112B: 16B-aligned, conflict-free)
#define ASTRIDE 136          // smem A row stride in halves (272B: 16B-aligned, conflict-free)

// ---------------------------- device scratch -------------------------------
__device__ __nv_bfloat16 g_Wt0[(size_t)4096 * 2048];   // layer0: [r][k] bf16
__device__ __nv_bfloat16 g_Wt1[(size_t)4096 * 2048];   // layer1
__device__ __nv_bfloat16 g_emb[(size_t)S_ * B_ * H_];  // [t][b][k]
__device__ __nv_bfloat16 g_h0[(size_t)(S_ + 1) * B_ * H_]; // [t][b][k]
__device__ __nv_bfloat16 g_h1[(size_t)(S_ + 1) * B_ * H_];
__device__ unsigned g_cnt0;
__device__ unsigned g_cnt1;

// ---------------------------- smem layout ----------------------------------
struct SmemLSTM {
    __nv_bfloat16 B[32][BSTRIDE];      // 131584 B : full B tile [b][k] for one step
    __nv_bfloat16 A[2][64][ASTRIDE];   //  34816 B : double-buffered A chunks [row][k]
    float         z[4][16][33];        //   8448 B : z staging [gate][u][b]
};
// total 174848 B -> 1 CTA / SM

// ---------------------------- helpers ---------------------------------------
__device__ __forceinline__ unsigned smem_u32(const void* p) {
    return (unsigned)__cvta_generic_to_shared(p);
}

__device__ __forceinline__ void cp16(void* dst, const void* src) {
    unsigned d = smem_u32(dst);
    asm volatile("cp.async.cg.shared.global [%0], [%1], 16;\n" :: "r"(d), "l"(src) : "memory");
}

__device__ __forceinline__ unsigned ld_acq(const unsigned* p) {
    unsigned v;
    asm volatile("ld.acquire.gpu.global.u32 %0, [%1];" : "=r"(v) : "l"(p) : "memory");
    return v;
}

__device__ __forceinline__ void load_A_chunk(SmemLSTM* S, const __nv_bfloat16* Wt,
                                             int cg, int chunk, int buf, int tid) {
    // 64 rows x 128 halves = 1024 x 16B units; 8 units per thread
    const __nv_bfloat16* base = Wt + (size_t)cg * 64 * KTOT + chunk * KCHUNK;
    #pragma unroll
    for (int m = 0; m < 8; ++m) {
        int c   = tid + (m << 7);     // 0..1023
        int row = c >> 4;             // 0..63
        int seg = (c & 15) << 3;      // halves: 0..120 step 8
        cp16(&S->A[buf][row][seg], base + (size_t)row * KTOT + seg);
    }
}

// ---------------------------- prep kernels ----------------------------------
__global__ void prep_weights(const float* __restrict__ Wx, const float* __restrict__ Wh,
                             int layer) {
    __nv_bfloat16* __restrict__ Wt = layer ? g_Wt1 : g_Wt0;
    const size_t n = (size_t)4096 * 2048;
    for (size_t idx = (size_t)blockIdx.x * blockDim.x + threadIdx.x; idx < n;
         idx += (size_t)gridDim.x * blockDim.x) {
        int r = (int)(idx >> 11);
        int k = (int)(idx & 2047);
        int cgp = r >> 6, rem = r & 63;
        int gate = rem >> 4, uu = rem & 15;
        int j = gate * H_ + cgp * 16 + uu;   // column in original [K][4096] weight
        float v = (k < H_) ? Wx[(size_t)k * 4096 + j]
                           : Wh[(size_t)(k - H_) * 4096 + j];
        Wt[idx] = __float2bfloat16(v);
    }
}

__global__ void prep_embed(const int* __restrict__ x, const float* __restrict__ emb) {
    const size_t n = (size_t)S_ * B_ * H_;
    for (size_t idx = (size_t)blockIdx.x * blockDim.x + threadIdx.x; idx < n;
         idx += (size_t)gridDim.x * blockDim.x) {
        int t   = (int)(idx >> 15);
        int rem = (int)(idx & 32767);
        int b   = rem >> 10;
        int k   = rem & 1023;
        int tok = x[b * S_ + t];   // x is [B][S]
        g_emb[idx] = __float2bfloat16(emb[(size_t)tok * H_ + k]);
    }
}

__global__ void prep_init() {
    const int n = B_ * H_;
    for (int idx = blockIdx.x * blockDim.x + threadIdx.x; idx < n;
         idx += gridDim.x * blockDim.x) {
        g_h0[idx] = __float2bfloat16(0.f);
        g_h1[idx] = __float2bfloat16(0.f);
    }
    if (blockIdx.x == 0 && threadIdx.x == 0) { g_cnt0 = 0u; g_cnt1 = 0u; }
}

// ---------------------------- persistent LSTM -------------------------------
__global__ void __launch_bounds__(128, 1)
lstm_persistent(const float* __restrict__ bias0, const float* __restrict__ bias1) {
    extern __shared__ __align__(16) char smem_raw[];
    SmemLSTM* S = reinterpret_cast<SmemLSTM*>(smem_raw);

    const int tid  = threadIdx.x;
    const int lane = tid & 31;
    const int g    = tid >> 5;                 // warp index == gate index (i,f,g,o)
    const int cta  = blockIdx.x;
    const bool l1  = (cta >= GPL);
    const int cg   = l1 ? (cta - GPL) : cta;   // 0..63, owns hidden units [cg*16, cg*16+16)

    const __nv_bfloat16* __restrict__ Wt  = l1 ? g_Wt1 : g_Wt0;
    const float* __restrict__ bias        = l1 ? bias1 : bias0;
    unsigned* myCnt                       = l1 ? &g_cnt1 : &g_cnt0;
    __nv_bfloat16* hout                   = l1 ? g_h1 : g_h0;

    // cell-update ownership: thread -> one hidden unit u, four batches
    const int u_loc = tid >> 3;                // 0..15
    const int u_g   = cg * 16 + u_loc;
    const int bb    = (tid & 7) << 2;          // batch base 0..28
    const float bi  = bias[u_g];
    const float bf_ = bias[H_ + u_g];
    const float bg_ = bias[2 * H_ + u_g];
    const float bo_ = bias[3 * H_ + u_g];
    float c_st[4] = {0.f, 0.f, 0.f, 0.f};

    // ldmatrix lane addressing (constant per thread)
    const int a_row  = g * 16 + (lane & 15);
    const int a_kofs = (lane < 16) ? 0 : 8;
    const int l16    = lane & 15;
    const int b_rloc = l16 & 7;
    const int b_kofs = (l16 >> 3) << 3;

    for (int t = 0; t < S_; ++t) {
        // ---- acquire: wait for producers ----
        if (tid == 0) {
            if (!l1) {
                const unsigned tgt = 64u * (unsigned)t;          // peers' step t-1 done
                while (ld_acq(&g_cnt0) < tgt) __nanosleep(64);
            } else {
                const unsigned tgt0 = 64u * (unsigned)(t + 1);   // h0[t+1] available
                while (ld_acq(&g_cnt0) < tgt0) __nanosleep(64);
                const unsigned tgt1 = 64u * (unsigned)t;         // h1[t] available
                while (ld_acq(&g_cnt1) < tgt1) __nanosleep(64);
            }
        }
        __syncthreads();
        __threadfence();

        // ---- B tile: [b][k] = concat(x_input, h_hidden), 128KB via cp.async ----
        const __nv_bfloat16* __restrict__ srcX =
            l1 ? (g_h0 + (size_t)(t + 1) * (B_ * H_)) : (g_emb + (size_t)t * (B_ * H_));
        const __nv_bfloat16* __restrict__ srcH =
            l1 ? (g_h1 + (size_t)t * (B_ * H_)) : (g_h0 + (size_t)t * (B_ * H_));
        #pragma unroll
        for (int m = 0; m < 64; ++m) {
            int c = tid + (m << 7);          // 0..8191 16B units
            int b = c >> 8;                  // 0..31
            int k = (c & 255) << 3;          // 0..2040 halves
            const __nv_bfloat16* src =
                (k < H_) ? (srcX + b * H_ + k) : (srcH + b * H_ + (k - H_));
            cp16(&S->B[b][k], src);
        }
        asm volatile("cp.async.commit_group;\n" ::: "memory");   // group: B
        load_A_chunk(S, Wt, cg, 0, 0, tid);
        asm volatile("cp.async.commit_group;\n" ::: "memory");   // group: A0

        float acc[4][4];
        #pragma unroll
        for (int nt = 0; nt < 4; ++nt)
            #pragma unroll
            for (int q = 0; q < 4; ++q) acc[nt][q] = 0.f;

        // ---- K loop: 16 chunks of 128, double-buffered A ----
        for (int i = 0; i < NCHUNK; ++i) {
            const int buf = i & 1;
            if (i + 1 < NCHUNK) {
                load_A_chunk(S, Wt, cg, i + 1, (i + 1) & 1, tid);
                asm volatile("cp.async.commit_group;\n" ::: "memory");
                asm volatile("cp.async.wait_group 1;\n" ::: "memory");
            } else {
                asm volatile("cp.async.wait_group 0;\n" ::: "memory");
            }
            __syncthreads();

            #pragma unroll
            for (int kt = 0; kt < KCHUNK / 16; ++kt) {
                unsigned a0, a1, a2, a3;
                {
                    unsigned addr = smem_u32(&S->A[buf][a_row][kt * 16 + a_kofs]);
                    asm volatile(
                        "ldmatrix.sync.aligned.m8n8.x4.shared.b16 {%0,%1,%2,%3}, [%4];\n"
                        : "=r"(a0), "=r"(a1), "=r"(a2), "=r"(a3) : "r"(addr));
                }
                const int kglob = i * KCHUNK + kt * 16;
                #pragma unroll
                for (int nt = 0; nt < 4; ++nt) {
                    unsigned bq0, bq1;
                    unsigned baddr = smem_u32(&S->B[nt * 8 + b_rloc][kglob + b_kofs]);
                    asm volatile(
                        "ldmatrix.sync.aligned.m8n8.x2.shared.b16 {%0,%1}, [%2];\n"
                        : "=r"(bq0), "=r"(bq1) : "r"(baddr));
                    asm volatile(
                        "mma.sync.aligned.m16n8k16.row.col.f32.bf16.bf16.f32 "
                        "{%0,%1,%2,%3}, {%4,%5,%6,%7}, {%8,%9}, {%0,%1,%2,%3};\n"
                        : "+f"(acc[nt][0]), "+f"(acc[nt][1]),
                          "+f"(acc[nt][2]), "+f"(acc[nt][3])
                        : "r"(a0), "r"(a1), "r"(a2), "r"(a3), "r"(bq0), "r"(bq1));
                }
            }
            __syncthreads();
        }

        // ---- stage z to smem: warp g -> z[g][u][b] ----
        {
            const int r  = lane >> 2;
            const int cb = (lane & 3) << 1;
            #pragma unroll
            for (int nt = 0; nt < 4; ++nt) {
                S->z[g][r][nt * 8 + cb]         = acc[nt][0];
                S->z[g][r][nt * 8 + cb + 1]     = acc[nt][1];
                S->z[g][r + 8][nt * 8 + cb]     = acc[nt][2];
                S->z[g][r + 8][nt * 8 + cb + 1] = acc[nt][3];
            }
        }
        __syncthreads();

        // ---- LSTM cell update (fp32, c-state in registers) ----
        __nv_bfloat16* hw = hout + (size_t)(t + 1) * (B_ * H_);
        #pragma unroll
        for (int j = 0; j < 4; ++j) {
            const int b = bb + j;
            float zi = S->z[0][u_loc][b] + bi;
            float zf = S->z[1][u_loc][b] + bf_;
            float zg = S->z[2][u_loc][b] + bg_;
            float zo = S->z[3][u_loc][b] + bo_;
            float ig = 1.f / (1.f + __expf(-zi));
            float fg = 1.f / (1.f + __expf(-zf));
            float og = 1.f / (1.f + __expf(-zo));
            float gc = tanhf(zg);
            c_st[j] = fg * c_st[j] + ig * gc;
            hw[b * H_ + u_g] = __float2bfloat16(og * tanhf(c_st[j]));
        }

        // ---- release ----
        __threadfence();
        __syncthreads();
        if (tid == 0) atomicAdd(myCnt, 1u);
    }
}

// ---------------------------- FC + softmax ----------------------------------
__global__ void fc_kernel(const float* __restrict__ Wfc, const float* __restrict__ bfc,
                          float* __restrict__ out) {
    __shared__ float hs[32][129];
    const int tidx = threadIdx.x;
    const int v = blockIdx.x * 256 + tidx;   // grid = 125 -> exactly 32000
    float acc[32];
    #pragma unroll
    for (int b = 0; b < 32; ++b) acc[b] = 0.f;

    const __nv_bfloat16* __restrict__ h1 = g_h1 + (size_t)S_ * B_ * H_;
    for (int kt = 0; kt < 8; ++kt) {
        __syncthreads();
        for (int e = tidx; e < 32 * 128; e += 256) {
            int b = e >> 7, kk = e & 127;
            hs[b][kk] = __bfloat162float(h1[b * H_ + kt * 128 + kk]);
        }
        __syncthreads();
        const float* w = Wfc + (size_t)(kt * 128) * V_ + v;
        #pragma unroll 4
        for (int kk = 0; kk < 128; ++kk) {
            float wv = w[(size_t)kk * V_];
            #pragma unroll
            for (int b = 0; b < 32; ++b) acc[b] += hs[b][kk] * wv;
        }
    }
    const float bias = bfc[v];
    #pragma unroll
    for (int b = 0; b < 32; ++b) out[(size_t)b * V_ + v] = acc[b] + bias;
}

__global__ void softmax_kernel(float* __restrict__ out) {
    const int b = blockIdx.x;                 // 32 rows
    float* row = out + (size_t)b * V_;
    __shared__ float sdata[32];
    const int tid = threadIdx.x;

    float m = -3.4e38f;
    for (int v = tid; v < V_; v += 256) m = fmaxf(m, row[v]);
    #pragma unroll
    for (int o = 16; o; o >>= 1) m = fmaxf(m, __shfl_xor_sync(0xffffffffu, m, o));
    if ((tid & 31) == 0) sdata[tid >> 5] = m;
    __syncthreads();
    if (tid == 0) {
        float mm = sdata[0];
        for (int i = 1; i < 8; ++i) mm = fmaxf(mm, sdata[i]);
        sdata[16] = mm;
    }
    __syncthreads();
    m = sdata[16];

    float s = 0.f;
    for (int v = tid; v < V_; v += 256) s += expf(row[v] - m);
    #pragma unroll
    for (int o = 16; o; o >>= 1) s += __shfl_xor_sync(0xffffffffu, s, o);
    if ((tid & 31) == 0) sdata[tid >> 5] = s;
    __syncthreads();
    if (tid == 0) {
        float ss = 0.f;
        for (int i = 0; i < 8; ++i) ss += sdata[i];
        sdata[17] = ss;
    }
    __syncthreads();
    const float inv = 1.f / sdata[17];

    for (int v = tid; v < V_; v += 256) row[v] = expf(row[v] - m) * inv;
}

// ---------------------------- launch -----------------------------------------
extern "C" void kernel_launch(void* const* d_in, const int* in_sizes, int n_in,
                              void* d_out, int out_size) {
    const int*   x   = (const int*)d_in[0];
    const float* emb = (const float*)d_in[1];
    const float* Wx0 = (const float*)d_in[2];
    const float* Wh0 = (const float*)d_in[3];
    const float* b0  = (const float*)d_in[4];
    const float* Wx1 = (const float*)d_in[5];
    const float* Wh1 = (const float*)d_in[6];
    const float* b1  = (const float*)d_in[7];
    const float* Wfc = (const float*)d_in[8];
    const float* bfc = (const float*)d_in[9];
    float* out = (float*)d_out;

    cudaFuncSetAttribute(lstm_persistent,
                         cudaFuncAttributeMaxDynamicSharedMemorySize,
                         (int)sizeof(SmemLSTM));

    prep_weights<<<2048, 256>>>(Wx0, Wh0, 0);
    prep_weights<<<2048, 256>>>(Wx1, Wh1, 1);
    prep_embed<<<2048, 256>>>(x, emb);
    prep_init<<<64, 256>>>();
    lstm_persistent<<<128, 128, sizeof(SmemLSTM)>>>(b0, b1);
    fc_kernel<<<125, 256>>>(Wfc, bfc, out);
    softmax_kernel<<<32, 256>>>(out);
}

// round 7
// speedup vs baseline: 1.4168x; 1.4168x over previous
#include <cuda_runtime.h>
#include <cuda_fp16.h>
#include <cuda_fp8.h>

// 2-layer LSTM LM, B=32,S=512,H=1024,V=32000.  fp8 weights resident in smem.
#define B_   32
#define S_   512
#define H_   1024
#define V_   32000
#define GPL  64
#define HSLOT 32768

__device__ unsigned char g_W0[(size_t)4096 * 2048];   // fp8 e4m3 x16, permuted
__device__ unsigned char g_W1[(size_t)4096 * 2048];
__device__ __half g_emb[(size_t)S_ * HSLOT];
__device__ __half g_h0[(size_t)(S_ + 1) * HSLOT];
__device__ __half g_h1[(size_t)(S_ + 1) * HSLOT];
__device__ unsigned g_cnt0;
__device__ unsigned g_cnt1;

struct Sm {
    unsigned char A[64][2064];    // 132096 B resident fp8 weights (stride pad 16)
    __half        B[2][32][264];  //  33792 B double-buffered activation chunk
    float         z[4][16][36];   //   9216 B gate staging [gate][u][b]
};                                // 175104 B total -> 1 CTA/SM

__device__ __forceinline__ unsigned smem_u32(const void* p) {
    return (unsigned)__cvta_generic_to_shared(p);
}
__device__ __forceinline__ void cp16(void* dst, const void* src) {
    unsigned d = smem_u32(dst);
    asm volatile("cp.async.cg.shared.global [%0], [%1], 16;\n" :: "r"(d), "l"(src) : "memory");
}
__device__ __forceinline__ unsigned ld_acq(const unsigned* p) {
    unsigned v;
    asm volatile("ld.acquire.gpu.global.u32 %0, [%1];" : "=r"(v) : "l"(p) : "memory");
    return v;
}
// 4 fp8 in one b32 -> two f16x2 regs (bytes 0,1 -> f0; bytes 2,3 -> f1)
__device__ __forceinline__ void cvt4(unsigned raw, unsigned& f0, unsigned& f1) {
    asm("{\n\t.reg .b16 l, h;\n\t"
        "mov.b32 {l, h}, %2;\n\t"
        "cvt.rn.f16x2.e4m3x2 %0, l;\n\t"
        "cvt.rn.f16x2.e4m3x2 %1, h;\n\t}"
        : "=r"(f0), "=r"(f1) : "r"(raw));
}

// ------------------------------- prep ---------------------------------------
__global__ void prep_weights(const float* __restrict__ Wx, const float* __restrict__ Wh,
                             int layer) {
    unsigned char* __restrict__ W = layer ? g_W1 : g_W0;
    const size_t n = (size_t)4096 * 2048;
    for (size_t idx = (size_t)blockIdx.x * blockDim.x + threadIdx.x; idx < n;
         idx += (size_t)gridDim.x * blockDim.x) {
        int r = (int)(idx >> 11);
        int k = (int)(idx & 2047);            // logical K
        int cgp = r >> 6, rem = r & 63;
        int gate = rem >> 4, uu = rem & 15;
        int j = gate * H_ + cgp * 16 + uu;    // column in original [K][4096]
        float v = (k < H_) ? Wx[(size_t)k * 4096 + j]
                           : Wh[(size_t)(k - H_) * 4096 + j];
        // permute within 32-byte K-group so ldmatrix.x4 + cvt -> exact a-frags
        int vlo = k & 31;
        int q = vlo >> 3, c = (vlo >> 1) & 3, o = vlo & 1;
        int phys = ((q >> 1) << 4) + (c << 2) + ((q & 1) << 1) + o;
        W[(size_t)r * 2048 + (k & ~31) + phys] =
            (unsigned char)__nv_cvt_float_to_fp8(v * 16.f, __NV_SATFINITE, __NV_E4M3);
    }
}

__global__ void prep_embed(const int* __restrict__ x, const float* __restrict__ emb) {
    const size_t n = (size_t)S_ * HSLOT;
    for (size_t idx = (size_t)blockIdx.x * blockDim.x + threadIdx.x; idx < n;
         idx += (size_t)gridDim.x * blockDim.x) {
        int t   = (int)(idx >> 15);
        int rem = (int)(idx & 32767);
        int b   = rem >> 10;
        int k   = rem & 1023;
        g_emb[idx] = __float2half(emb[(size_t)x[b * S_ + t] * H_ + k]);
    }
}

__global__ void prep_init() {
    for (int i = blockIdx.x * blockDim.x + threadIdx.x; i < HSLOT;
         i += gridDim.x * blockDim.x) {
        g_h0[i] = __float2half(0.f);
        g_h1[i] = __float2half(0.f);
    }
    if (blockIdx.x == 0 && threadIdx.x == 0) { g_cnt0 = 0u; g_cnt1 = 0u; }
}

// --------------------------- persistent LSTM --------------------------------
__global__ void __launch_bounds__(256, 1)
lstm_persistent(const float* __restrict__ bias0, const float* __restrict__ bias1) {
    extern __shared__ __align__(16) char smem_raw[];
    Sm* S = reinterpret_cast<Sm*>(smem_raw);

    const int tid  = threadIdx.x;
    const int lane = tid & 31;
    const int w    = tid >> 5;
    const int g    = w >> 1;                  // gate 0..3
    const int nh   = w & 1;                   // batch half
    const bool l1  = (blockIdx.x >= GPL);
    const int cg   = l1 ? (blockIdx.x - GPL) : blockIdx.x;

    const unsigned char* __restrict__ Wg = (l1 ? g_W1 : g_W0) + (size_t)cg * 64 * 2048;
    const float* __restrict__ bias = l1 ? bias1 : bias0;
    unsigned* myCnt = l1 ? &g_cnt1 : &g_cnt0;
    __half* hout = l1 ? g_h1 : g_h0;

    // ---- load resident weights (once) ----
    #pragma unroll
    for (int m = 0; m < 32; ++m) {
        int u   = tid + (m << 8);             // 0..8191 16B units
        int row = u >> 7;                     // 128 units per row
        int off = (u & 127) << 4;             // bytes
        cp16(&S->A[row][off], Wg + (size_t)row * 2048 + off);
    }
    asm volatile("cp.async.commit_group;\ncp.async.wait_group 0;\n" ::: "memory");
    __syncthreads();

    // ---- thread-constant addresses ----
    const unsigned aBase = smem_u32(&S->A[g * 16 + (lane & 15)][(lane >> 4) << 4]);
    const int bRow  = nh * 16 + ((lane >> 4) << 3) + (lane & 7);
    const int bKofs = ((lane >> 3) & 1) << 3;
    const unsigned bBase0 = smem_u32(&S->B[0][bRow][bKofs]);
    const unsigned bBase1 = smem_u32(&S->B[1][bRow][bKofs]);

    // ---- cell ownership: thread -> unit u_loc, 2 batches ----
    const int u_loc = tid >> 4;
    const int u_g   = cg * 16 + u_loc;
    const int bb    = (tid & 15) << 1;
    const float bi  = bias[u_g];
    const float bf_ = bias[H_ + u_g];
    const float bg_ = bias[2 * H_ + u_g];
    const float bo_ = bias[3 * H_ + u_g];
    float c_st[2] = {0.f, 0.f};

    for (int t = 0; t < S_; ++t) {
        // ---- acquire producers ----
        if (tid == 0) {
            if (!l1) {
                while (ld_acq(&g_cnt0) < 64u * (unsigned)t) __nanosleep(32);
            } else {
                while (ld_acq(&g_cnt0) < 64u * (unsigned)(t + 1)) __nanosleep(32);
                while (ld_acq(&g_cnt1) < 64u * (unsigned)t) __nanosleep(32);
            }
        }
        __syncthreads();
        __threadfence();

        const __half* __restrict__ srcX =
            l1 ? (g_h0 + (size_t)(t + 1) * HSLOT) : (g_emb + (size_t)t * HSLOT);
        const __half* __restrict__ srcH =
            l1 ? (g_h1 + (size_t)t * HSLOT) : (g_h0 + (size_t)t * HSLOT);

        // ---- prologue: chunks 0,1 (each 256 K x 32 b = 16 KB) ----
        #pragma unroll
        for (int c = 0; c < 2; ++c) {
            const __half* base = (c < 4) ? (srcX + c * 256) : (srcH + (c - 4) * 256);
            #pragma unroll
            for (int m = 0; m < 4; ++m) {
                int u = tid + (m << 8);           // 0..1023 units
                int b = u >> 5, off = (u & 31) << 3;
                cp16(&S->B[c][b][off], base + b * H_ + off);
            }
            asm volatile("cp.async.commit_group;\n" ::: "memory");
        }

        float acc[2][4] = {{0.f, 0.f, 0.f, 0.f}, {0.f, 0.f, 0.f, 0.f}};

        for (int c = 0; c < 8; ++c) {
            if (c < 7) asm volatile("cp.async.wait_group 1;\n" ::: "memory");
            else       asm volatile("cp.async.wait_group 0;\n" ::: "memory");
            __syncthreads();

            const unsigned aA = aBase + c * 256;
            const unsigned bA = (c & 1) ? bBase1 : bBase0;
            #pragma unroll
            for (int p = 0; p < 8; ++p) {
                unsigned ra0, ra1, ra2, ra3;
                asm volatile("ldmatrix.sync.aligned.m8n8.x4.shared.b16 {%0,%1,%2,%3}, [%4];\n"
                             : "=r"(ra0), "=r"(ra1), "=r"(ra2), "=r"(ra3)
                             : "r"(aA + p * 32));
                unsigned A0[4], A1[4];
                cvt4(ra0, A0[0], A0[2]);
                cvt4(ra1, A0[1], A0[3]);
                cvt4(ra2, A1[0], A1[2]);
                cvt4(ra3, A1[1], A1[3]);
                #pragma unroll
                for (int s = 0; s < 2; ++s) {
                    const unsigned* A = s ? A1 : A0;
                    unsigned b0, b1, b2, b3;
                    asm volatile("ldmatrix.sync.aligned.m8n8.x4.shared.b16 {%0,%1,%2,%3}, [%4];\n"
                                 : "=r"(b0), "=r"(b1), "=r"(b2), "=r"(b3)
                                 : "r"(bA + (p * 32 + s * 16) * 2));
                    asm volatile("mma.sync.aligned.m16n8k16.row.col.f32.f16.f16.f32 "
                                 "{%0,%1,%2,%3}, {%4,%5,%6,%7}, {%8,%9}, {%0,%1,%2,%3};\n"
                                 : "+f"(acc[0][0]), "+f"(acc[0][1]), "+f"(acc[0][2]), "+f"(acc[0][3])
                                 : "r"(A[0]), "r"(A[1]), "r"(A[2]), "r"(A[3]), "r"(b0), "r"(b1));
                    asm volatile("mma.sync.aligned.m16n8k16.row.col.f32.f16.f16.f32 "
                                 "{%0,%1,%2,%3}, {%4,%5,%6,%7}, {%8,%9}, {%0,%1,%2,%3};\n"
                                 : "+f"(acc[1][0]), "+f"(acc[1][1]), "+f"(acc[1][2]), "+f"(acc[1][3])
                                 : "r"(A[0]), "r"(A[1]), "r"(A[2]), "r"(A[3]), "r"(b2), "r"(b3));
                }
            }
            __syncthreads();

            if (c + 2 < 8) {
                const int cn = c + 2;
                const __half* base = (cn < 4) ? (srcX + cn * 256) : (srcH + (cn - 4) * 256);
                #pragma unroll
                for (int m = 0; m < 4; ++m) {
                    int u = tid + (m << 8);
                    int b = u >> 5, off = (u & 31) << 3;
                    cp16(&S->B[c & 1][b][off], base + b * H_ + off);
                }
                asm volatile("cp.async.commit_group;\n" ::: "memory");
            }
        }

        // ---- stage z ----
        {
            const int r  = lane >> 2;
            const int cb = nh * 16 + ((lane & 3) << 1);
            #pragma unroll
            for (int nt = 0; nt < 2; ++nt) {
                S->z[g][r][cb + nt * 8]         = acc[nt][0];
                S->z[g][r][cb + nt * 8 + 1]     = acc[nt][1];
                S->z[g][r + 8][cb + nt * 8]     = acc[nt][2];
                S->z[g][r + 8][cb + nt * 8 + 1] = acc[nt][3];
            }
        }
        __syncthreads();

        // ---- LSTM cell (fp32; 1/16 undoes the fp8 weight scale) ----
        __half* hw = hout + (size_t)(t + 1) * HSLOT;
        #pragma unroll
        for (int j = 0; j < 2; ++j) {
            const int b = bb + j;
            float zi = S->z[0][u_loc][b] * 0.0625f + bi;
            float zf = S->z[1][u_loc][b] * 0.0625f + bf_;
            float zg = S->z[2][u_loc][b] * 0.0625f + bg_;
            float zo = S->z[3][u_loc][b] * 0.0625f + bo_;
            float ig = 1.f / (1.f + __expf(-zi));
            float fg = 1.f / (1.f + __expf(-zf));
            float og = 1.f / (1.f + __expf(-zo));
            float gc = tanhf(zg);
            c_st[j] = fg * c_st[j] + ig * gc;
            hw[b * H_ + u_g] = __float2half(og * tanhf(c_st[j]));
        }

        // ---- release ----
        __threadfence();
        __syncthreads();
        if (tid == 0) atomicAdd(myCnt, 1u);
    }
}

// ----------------------------- FC + softmax ---------------------------------
__global__ void fc_kernel(const float* __restrict__ Wfc, const float* __restrict__ bfc,
                          float* __restrict__ out) {
    __shared__ float hs[32][129];
    const int tidx = threadIdx.x;
    const int v = blockIdx.x * 256 + tidx;
    float acc[32];
    #pragma unroll
    for (int b = 0; b < 32; ++b) acc[b] = 0.f;

    const __half* __restrict__ h1 = g_h1 + (size_t)S_ * HSLOT;
    for (int kt = 0; kt < 8; ++kt) {
        __syncthreads();
        for (int e = tidx; e < 32 * 128; e += 256) {
            int b = e >> 7, kk = e & 127;
            hs[b][kk] = __half2float(h1[b * H_ + kt * 128 + kk]);
        }
        __syncthreads();
        const float* w2 = Wfc + (size_t)(kt * 128) * V_ + v;
        #pragma unroll 4
        for (int kk = 0; kk < 128; ++kk) {
            float wv = w2[(size_t)kk * V_];
            #pragma unroll
            for (int b = 0; b < 32; ++b) acc[b] += hs[b][kk] * wv;
        }
    }
    const float bv = bfc[v];
    #pragma unroll
    for (int b = 0; b < 32; ++b) out[(size_t)b * V_ + v] = acc[b] + bv;
}

__global__ void softmax_kernel(float* __restrict__ out) {
    float* row = out + (size_t)blockIdx.x * V_;
    __shared__ float sd[32];
    const int tid = threadIdx.x;

    float m = -3.4e38f;
    for (int v = tid; v < V_; v += 256) m = fmaxf(m, row[v]);
    #pragma unroll
    for (int o = 16; o; o >>= 1) m = fmaxf(m, __shfl_xor_sync(0xffffffffu, m, o));
    if ((tid & 31) == 0) sd[tid >> 5] = m;
    __syncthreads();
    if (tid == 0) {
        float mm = sd[0];
        for (int i = 1; i < 8; ++i) mm = fmaxf(mm, sd[i]);
        sd[16] = mm;
    }
    __syncthreads();
    m = sd[16];

    float s = 0.f;
    for (int v = tid; v < V_; v += 256) s += expf(row[v] - m);
    #pragma unroll
    for (int o = 16; o; o >>= 1) s += __shfl_xor_sync(0xffffffffu, s, o);
    if ((tid & 31) == 0) sd[tid >> 5] = s;
    __syncthreads();
    if (tid == 0) {
        float ss = 0.f;
        for (int i = 0; i < 8; ++i) ss += sd[i];
        sd[17] = ss;
    }
    __syncthreads();
    const float inv = 1.f / sd[17];
    for (int v = tid; v < V_; v += 256) row[v] = expf(row[v] - m) * inv;
}

// ------------------------------- launch --------------------------------------
extern "C" void kernel_launch(void* const* d_in, const int* in_sizes, int n_in,
                              void* d_out, int out_size) {
    const int*   x   = (const int*)d_in[0];
    const float* emb = (const float*)d_in[1];
    const float* Wx0 = (const float*)d_in[2];
    const float* Wh0 = (const float*)d_in[3];
    const float* b0  = (const float*)d_in[4];
    const float* Wx1 = (const float*)d_in[5];
    const float* Wh1 = (const float*)d_in[6];
    const float* b1  = (const float*)d_in[7];
    const float* Wfc = (const float*)d_in[8];
    const float* bfc = (const float*)d_in[9];
    float* out = (float*)d_out;

    cudaFuncSetAttribute(lstm_persistent,
                         cudaFuncAttributeMaxDynamicSharedMemorySize, (int)sizeof(Sm));

    prep_weights<<<2048, 256>>>(Wx0, Wh0, 0);
    prep_weights<<<2048, 256>>>(Wx1, Wh1, 1);
    prep_embed<<<2048, 256>>>(x, emb);
    prep_init<<<64, 256>>>();
    lstm_persistent<<<128, 256, sizeof(Sm)>>>(b0, b1);
    fc_kernel<<<125, 256>>>(Wfc, bfc, out);
    softmax_kernel<<<32, 256>>>(out);
}

// round 9
// speedup vs baseline: 1.6755x; 1.1826x over previous
#include <cuda_runtime.h>
#include <cuda.h>
#include <cuda_fp16.h>
#include <cuda_fp8.h>

// 2-layer LSTM LM, B=32,S=512,H=1024,V=32000.
// fp8 weights resident in smem; activations streamed per step via TMA (SW128);
// K-phase split halves the sequential critical path.
#define B_   32
#define S_   512
#define H_   1024
#define V_   32000
#define GPL  64
#define HSLOT 32768

__device__ unsigned char g_W0[(size_t)4096 * 2048];   // fp8 e4m3 x16, permuted
__device__ unsigned char g_W1[(size_t)4096 * 2048];
__device__ __half g_emb[(size_t)S_ * HSLOT];           // [t*32+b][k]
__device__ __half g_h0[(size_t)(S_ + 1) * HSLOT];
__device__ __half g_h1[(size_t)(S_ + 1) * HSLOT];
__device__ unsigned g_cnt0;
__device__ unsigned g_cnt1;

struct Sm {
    unsigned char A[64][2064];        // 132096 B resident fp8 weights
    __half        Bt[2][4][32][64];   //  32768 B: 2 bufs x 4 kblocks x 32 rows x 128B (SW128)
    float         z[4][16][36];       //   9216 B gate staging
    unsigned long long mbar[2];
};                                    // ~174 KB -> 1 CTA/SM

// ------------------------------ helpers -------------------------------------
__device__ __forceinline__ unsigned smem_u32(const void* p) {
    return (unsigned)__cvta_generic_to_shared(p);
}
__device__ __forceinline__ void cp16(void* dst, const void* src) {
    unsigned d = smem_u32(dst);
    asm volatile("cp.async.cg.shared.global [%0], [%1], 16;\n" :: "r"(d), "l"(src) : "memory");
}
__device__ __forceinline__ unsigned ld_acq(const unsigned* p) {
    unsigned v;
    asm volatile("ld.acquire.gpu.global.u32 %0, [%1];" : "=r"(v) : "l"(p) : "memory");
    return v;
}
__device__ __forceinline__ void cvt4(unsigned raw, unsigned& f0, unsigned& f1) {
    asm("{\n\t.reg .b16 l, h;\n\t"
        "mov.b32 {l, h}, %2;\n\t"
        "cvt.rn.f16x2.e4m3x2 %0, l;\n\t"
        "cvt.rn.f16x2.e4m3x2 %1, h;\n\t}"
        : "=r"(f0), "=r"(f1) : "r"(raw));
}
__device__ __forceinline__ void mbar_init(unsigned a, unsigned c) {
    asm volatile("mbarrier.init.shared.b64 [%0], %1;" :: "r"(a), "r"(c) : "memory");
}
__device__ __forceinline__ void mbar_expect(unsigned a, unsigned bytes) {
    asm volatile("mbarrier.arrive.expect_tx.shared.b64 _, [%0], %1;" :: "r"(a), "r"(bytes) : "memory");
}
__device__ __forceinline__ void mbar_wait(unsigned a, unsigned ph) {
    asm volatile(
        "{\n\t.reg .pred P;\n"
        "W%=:\n\t"
        "mbarrier.try_wait.parity.acquire.cta.shared::cta.b64 P, [%0], %1, 0x989680;\n\t"
        "@!P bra W%=;\n\t}"
        :: "r"(a), "r"(ph) : "memory");
}
__device__ __forceinline__ void tma2d(unsigned dst, const CUtensorMap* m, int x, int y,
                                      unsigned mb) {
    asm volatile(
        "cp.async.bulk.tensor.2d.shared::cta.global.tile.mbarrier::complete_tx::bytes "
        "[%0], [%1, {%2, %3}], [%4];"
        :: "r"(dst), "l"(m), "r"(x), "r"(y), "r"(mb) : "memory");
}

// ------------------------------- prep ---------------------------------------
__global__ void prep_weights(const float* __restrict__ Wx, const float* __restrict__ Wh,
                             int layer) {
    unsigned char* __restrict__ W = layer ? g_W1 : g_W0;
    const size_t n = (size_t)4096 * 2048;
    for (size_t idx = (size_t)blockIdx.x * blockDim.x + threadIdx.x; idx < n;
         idx += (size_t)gridDim.x * blockDim.x) {
        int r = (int)(idx >> 11);
        int k = (int)(idx & 2047);
        int cgp = r >> 6, rem = r & 63;
        int gate = rem >> 4, uu = rem & 15;
        int j = gate * H_ + cgp * 16 + uu;
        float v = (k < H_) ? Wx[(size_t)k * 4096 + j]
                           : Wh[(size_t)(k - H_) * 4096 + j];
        int vlo = k & 31;
        int q = vlo >> 3, c = (vlo >> 1) & 3, o = vlo & 1;
        int phys = ((q >> 1) << 4) + (c << 2) + ((q & 1) << 1) + o;
        W[(size_t)r * 2048 + (k & ~31) + phys] =
            (unsigned char)__nv_cvt_float_to_fp8(v * 16.f, __NV_SATFINITE, __NV_E4M3);
    }
}

__global__ void prep_embed(const int* __restrict__ x, const float* __restrict__ emb) {
    const size_t n = (size_t)S_ * HSLOT;
    for (size_t idx = (size_t)blockIdx.x * blockDim.x + threadIdx.x; idx < n;
         idx += (size_t)gridDim.x * blockDim.x) {
        int t   = (int)(idx >> 15);
        int rem = (int)(idx & 32767);
        int b   = rem >> 10;
        int k   = rem & 1023;
        g_emb[idx] = __float2half(emb[(size_t)x[b * S_ + t] * H_ + k]);
    }
}

__global__ void prep_init() {
    for (int i = blockIdx.x * blockDim.x + threadIdx.x; i < HSLOT;
         i += gridDim.x * blockDim.x) {
        g_h0[i] = __float2half(0.f);
        g_h1[i] = __float2half(0.f);
    }
    if (blockIdx.x == 0 && threadIdx.x == 0) { g_cnt0 = 0u; g_cnt1 = 0u; }
}

// --------------------------- persistent LSTM --------------------------------
__device__ __forceinline__ void issue_chunk(int c, int buf, int t, bool l1,
                                            unsigned btAddr, unsigned mbAddr,
                                            const CUtensorMap* mE,
                                            const CUtensorMap* mH0,
                                            const CUtensorMap* mH1) {
    unsigned mb = mbAddr + buf * 8;
    mbar_expect(mb, 16384u);
    const CUtensorMap* m;
    int x, y;
    if (c < 4) { m = l1 ? mH0 : mE;  y = (l1 ? (t + 1) : t) * 32; x = c * 256; }
    else       { m = l1 ? mH1 : mH0; y = t * 32;                  x = (c - 4) * 256; }
    unsigned d = btAddr + buf * 16384;
    #pragma unroll
    for (int j = 0; j < 4; ++j)
        tma2d(d + j * 4096, m, x + j * 64, y, mb);
}

__global__ void __launch_bounds__(256, 1)
lstm_persistent(const __grid_constant__ CUtensorMap mE,
                const __grid_constant__ CUtensorMap mH0,
                const __grid_constant__ CUtensorMap mH1,
                const float* __restrict__ bias0, const float* __restrict__ bias1) {
    extern __shared__ __align__(1024) char smem_raw[];
    Sm* S = reinterpret_cast<Sm*>(smem_raw);

    const int tid  = threadIdx.x;
    const int lane = tid & 31;
    const int w    = tid >> 5;
    const int g    = w >> 1;
    const int nh   = w & 1;
    const bool l1  = (blockIdx.x >= GPL);
    const int cg   = l1 ? (blockIdx.x - GPL) : blockIdx.x;

    const unsigned char* __restrict__ Wg = (l1 ? g_W1 : g_W0) + (size_t)cg * 64 * 2048;
    const float* __restrict__ bias = l1 ? bias1 : bias0;
    unsigned* myCnt = l1 ? &g_cnt1 : &g_cnt0;
    __half* hout = l1 ? g_h1 : g_h0;

    // ---- resident weights (once) ----
    #pragma unroll
    for (int m = 0; m < 32; ++m) {
        int u   = tid + (m << 8);
        int row = u >> 7;
        int off = (u & 127) << 4;
        cp16(&S->A[row][off], Wg + (size_t)row * 2048 + off);
    }
    asm volatile("cp.async.commit_group;\ncp.async.wait_group 0;\n" ::: "memory");

    const unsigned mbAddr = smem_u32(&S->mbar[0]);
    const unsigned btAddr = smem_u32(&S->Bt[0][0][0][0]);
    if (tid == 0) { mbar_init(mbAddr, 1); mbar_init(mbAddr + 8, 1); }
    asm volatile("fence.proxy.async.shared::cta;" ::: "memory");
    __syncthreads();

    // ---- thread-constant addressing ----
    const unsigned aBase = smem_u32(&S->A[g * 16 + (lane & 15)][(lane >> 4) << 4]);
    const int bRow   = nh * 16 + ((lane >> 4) << 3) + (lane & 7);
    const unsigned bk1 = (lane >> 3) & 1;
    const unsigned xorr = (unsigned)(bRow & 7);
    const unsigned rowOff = (unsigned)bRow * 128;

    const int u_loc = tid >> 4;
    const int u_g   = cg * 16 + u_loc;
    const int bb    = (tid & 15) << 1;
    const float bi  = bias[u_g];
    const float bf_ = bias[H_ + u_g];
    const float bg_ = bias[2 * H_ + u_g];
    const float bo_ = bias[3 * H_ + u_g];
    float c_st[2] = {0.f, 0.f};

    unsigned phb0 = 0, phb1 = 0;

    for (int t = 0; t < S_; ++t) {
        float acc[2][4] = {{0.f, 0.f, 0.f, 0.f}, {0.f, 0.f, 0.f, 0.f}};

        #pragma unroll
        for (int ph = 0; ph < 2; ++ph) {
            // ---- acquire producers for this phase ----
            if (tid == 0) {
                if (!l1) {
                    if (ph == 1)
                        while (ld_acq(&g_cnt0) < 64u * (unsigned)t) __nanosleep(32);
                } else {
                    if (ph == 0)
                        while (ld_acq(&g_cnt1) < 64u * (unsigned)t) __nanosleep(32);
                    else
                        while (ld_acq(&g_cnt0) < 64u * (unsigned)(t + 1)) __nanosleep(32);
                }
            }
            __syncthreads();

            // chunk order: l0 ph0 -> 0..3 (emb), ph1 -> 4..7 (h0[t])
            //              l1 ph0 -> 4..7 (h1[t]), ph1 -> 0..3 (h0[t+1])
            const int cstart = l1 ? (ph ? 0 : 4) : (ph ? 4 : 0);

            if (tid == 0) {
                issue_chunk(cstart + 0, 0, t, l1, btAddr, mbAddr, &mE, &mH0, &mH1);
                issue_chunk(cstart + 1, 1, t, l1, btAddr, mbAddr, &mE, &mH0, &mH1);
            }

            #pragma unroll
            for (int i = 0; i < 4; ++i) {
                const int buf = i & 1;
                const int c   = cstart + i;

                if (buf == 0) { mbar_wait(mbAddr, phb0);     phb0 ^= 1; }
                else          { mbar_wait(mbAddr + 8, phb1); phb1 ^= 1; }

                const unsigned aA0  = aBase + c * 256;
                const unsigned bufB = btAddr + buf * 16384 + rowOff;
                #pragma unroll
                for (int p = 0; p < 8; ++p) {
                    unsigned ra0, ra1, ra2, ra3;
                    asm volatile("ldmatrix.sync.aligned.m8n8.x4.shared.b16 {%0,%1,%2,%3}, [%4];\n"
                                 : "=r"(ra0), "=r"(ra1), "=r"(ra2), "=r"(ra3)
                                 : "r"(aA0 + p * 32));
                    unsigned A0[4], A1[4];
                    cvt4(ra0, A0[0], A0[2]);
                    cvt4(ra1, A0[1], A0[3]);
                    cvt4(ra2, A1[0], A1[2]);
                    cvt4(ra3, A1[1], A1[3]);
                    #pragma unroll
                    for (int s = 0; s < 2; ++s) {
                        const unsigned* A = s ? A1 : A0;
                        const unsigned kq = ((p & 1) << 2) | (s << 1) | bk1;
                        const unsigned bA = bufB + ((p >> 1) << 12) + ((kq ^ xorr) << 4);
                        unsigned b0, b1, b2, b3;
                        asm volatile("ldmatrix.sync.aligned.m8n8.x4.shared.b16 {%0,%1,%2,%3}, [%4];\n"
                                     : "=r"(b0), "=r"(b1), "=r"(b2), "=r"(b3)
                                     : "r"(bA));
                        asm volatile("mma.sync.aligned.m16n8k16.row.col.f32.f16.f16.f32 "
                                     "{%0,%1,%2,%3}, {%4,%5,%6,%7}, {%8,%9}, {%0,%1,%2,%3};\n"
                                     : "+f"(acc[0][0]), "+f"(acc[0][1]), "+f"(acc[0][2]), "+f"(acc[0][3])
                                     : "r"(A[0]), "r"(A[1]), "r"(A[2]), "r"(A[3]), "r"(b0), "r"(b1));
                        asm volatile("mma.sync.aligned.m16n8k16.row.col.f32.f16.f16.f32 "
                                     "{%0,%1,%2,%3}, {%4,%5,%6,%7}, {%8,%9}, {%0,%1,%2,%3};\n"
                                     : "+f"(acc[1][0]), "+f"(acc[1][1]), "+f"(acc[1][2]), "+f"(acc[1][3])
                                     : "r"(A[0]), "r"(A[1]), "r"(A[2]), "r"(A[3]), "r"(b2), "r"(b3));
                    }
                }
                __syncthreads();   // all readers done before buffer reuse
                if (tid == 0 && i < 2)
                    issue_chunk(cstart + i + 2, buf, t, l1, btAddr, mbAddr, &mE, &mH0, &mH1);
            }
        }

        // ---- stage z ----
        {
            const int r  = lane >> 2;
            const int cb = nh * 16 + ((lane & 3) << 1);
            #pragma unroll
            for (int nt = 0; nt < 2; ++nt) {
                S->z[g][r][cb + nt * 8]         = acc[nt][0];
                S->z[g][r][cb + nt * 8 + 1]     = acc[nt][1];
                S->z[g][r + 8][cb + nt * 8]     = acc[nt][2];
                S->z[g][r + 8][cb + nt * 8 + 1] = acc[nt][3];
            }
        }
        __syncthreads();

        // ---- LSTM cell (fp32; 1/16 undoes fp8 weight scale) ----
        __half* hw = hout + (size_t)(t + 1) * HSLOT;
        #pragma unroll
        for (int j = 0; j < 2; ++j) {
            const int b = bb + j;
            float zi = S->z[0][u_loc][b] * 0.0625f + bi;
            float zf = S->z[1][u_loc][b] * 0.0625f + bf_;
            float zg = S->z[2][u_loc][b] * 0.0625f + bg_;
            float zo = S->z[3][u_loc][b] * 0.0625f + bo_;
            float ig = 1.f / (1.f + __expf(-zi));
            float fg = 1.f / (1.f + __expf(-zf));
            float og = 1.f / (1.f + __expf(-zo));
            float gc = tanhf(zg);
            c_st[j] = fg * c_st[j] + ig * gc;
            hw[b * H_ + u_g] = __float2half(og * tanhf(c_st[j]));
        }

        // ---- release ----
        __threadfence();
        __syncthreads();
        if (tid == 0) atomicAdd(myCnt, 1u);
    }
}

// ----------------------------- FC + softmax ---------------------------------
__global__ void fc_kernel(const float* __restrict__ Wfc, const float* __restrict__ bfc,
                          float* __restrict__ out) {
    __shared__ float hs[32][129];
    const int tidx = threadIdx.x;
    const int v = blockIdx.x * 256 + tidx;
    float acc[32];
    #pragma unroll
    for (int b = 0; b < 32; ++b) acc[b] = 0.f;

    const __half* __restrict__ h1 = g_h1 + (size_t)S_ * HSLOT;
    for (int kt = 0; kt < 8; ++kt) {
        __syncthreads();
        for (int e = tidx; e < 32 * 128; e += 256) {
            int b = e >> 7, kk = e & 127;
            hs[b][kk] = __half2float(h1[b * H_ + kt * 128 + kk]);
        }
        __syncthreads();
        const float* w2 = Wfc + (size_t)(kt * 128) * V_ + v;
        #pragma unroll 4
        for (int kk = 0; kk < 128; ++kk) {
            float wv = w2[(size_t)kk * V_];
            #pragma unroll
            for (int b = 0; b < 32; ++b) acc[b] += hs[b][kk] * wv;
        }
    }
    const float bv = bfc[v];
    #pragma unroll
    for (int b = 0; b < 32; ++b) out[(size_t)b * V_ + v] = acc[b] + bv;
}

__global__ void softmax_kernel(float* __restrict__ out) {
    float* row = out + (size_t)blockIdx.x * V_;
    __shared__ float sd[32];
    const int tid = threadIdx.x;

    float m = -3.4e38f;
    for (int v = tid; v < V_; v += 256) m = fmaxf(m, row[v]);
    #pragma unroll
    for (int o = 16; o; o >>= 1) m = fmaxf(m, __shfl_xor_sync(0xffffffffu, m, o));
    if ((tid & 31) == 0) sd[tid >> 5] = m;
    __syncthreads();
    if (tid == 0) {
        float mm = sd[0];
        for (int i = 1; i < 8; ++i) mm = fmaxf(mm, sd[i]);
        sd[16] = mm;
    }
    __syncthreads();
    m = sd[16];

    float s = 0.f;
    for (int v = tid; v < V_; v += 256) s += expf(row[v] - m);
    #pragma unroll
    for (int o = 16; o; o >>= 1) s += __shfl_xor_sync(0xffffffffu, s, o);
    if ((tid & 31) == 0) sd[tid >> 5] = s;
    __syncthreads();
    if (tid == 0) {
        float ss = 0.f;
        for (int i = 0; i < 8; ++i) ss += sd[i];
        sd[17] = ss;
    }
    __syncthreads();
    const float inv = 1.f / sd[17];
    for (int v = tid; v < V_; v += 256) row[v] = expf(row[v] - m) * inv;
}

// ------------------------------- launch --------------------------------------
typedef CUresult (CUDAAPI *tmap_fn_t)(CUtensorMap*, CUtensorMapDataType, cuuint32_t,
                                      void*, const cuuint64_t*, const cuuint64_t*,
                                      const cuuint32_t*, const cuuint32_t*,
                                      CUtensorMapInterleave, CUtensorMapSwizzle,
                                      CUtensorMapL2promotion, CUtensorMapFloatOOBfill);

static void make_map(tmap_fn_t fn, CUtensorMap* m, void* base, unsigned long long rows) {
    cuuint64_t dims[2]    = {1024ull, rows};
    cuuint64_t strides[1] = {2048ull};
    cuuint32_t box[2]     = {64u, 32u};
    cuuint32_t es[2]      = {1u, 1u};
    fn(m, CU_TENSOR_MAP_DATA_TYPE_FLOAT16, 2, base, dims, strides, box, es,
       CU_TENSOR_MAP_INTERLEAVE_NONE, CU_TENSOR_MAP_SWIZZLE_128B,
       CU_TENSOR_MAP_L2_PROMOTION_L2_128B, CU_TENSOR_MAP_FLOAT_OOB_FILL_NONE);
}

extern "C" void kernel_launch(void* const* d_in, const int* in_sizes, int n_in,
                              void* d_out, int out_size) {
    const int*   x   = (const int*)d_in[0];
    const float* emb = (const float*)d_in[1];
    const float* Wx0 = (const float*)d_in[2];
    const float* Wh0 = (const float*)d_in[3];
    const float* b0  = (const float*)d_in[4];
    const float* Wx1 = (const float*)d_in[5];
    const float* Wh1 = (const float*)d_in[6];
    const float* b1  = (const float*)d_in[7];
    const float* Wfc = (const float*)d_in[8];
    const float* bfc = (const float*)d_in[9];
    float* out = (float*)d_out;

    // tensor maps (driver entry point via runtime API; no -lcuda needed)
    tmap_fn_t fn = nullptr;
    cudaDriverEntryPointQueryResult st;
    cudaGetDriverEntryPointByVersion("cuTensorMapEncodeTiled", (void**)&fn, 12050,
                                     cudaEnableDefault, &st);
    void *pE = nullptr, *pH0 = nullptr, *pH1 = nullptr;
    cudaGetSymbolAddress(&pE, g_emb);
    cudaGetSymbolAddress(&pH0, g_h0);
    cudaGetSymbolAddress(&pH1, g_h1);
    CUtensorMap mE, mH0, mH1;
    make_map(fn, &mE, pE, (unsigned long long)S_ * 32ull);
    make_map(fn, &mH0, pH0, (unsigned long long)(S_ + 1) * 32ull);
    make_map(fn, &mH1, pH1, (unsigned long long)(S_ + 1) * 32ull);

    cudaFuncSetAttribute(lstm_persistent,
                         cudaFuncAttributeMaxDynamicSharedMemorySize, (int)sizeof(Sm));

    prep_weights<<<2048, 256>>>(Wx0, Wh0, 0);
    prep_weights<<<2048, 256>>>(Wx1, Wh1, 1);
    prep_embed<<<2048, 256>>>(x, emb);
    prep_init<<<64, 256>>>();
    lstm_persistent<<<128, 256, sizeof(Sm)>>>(mE, mH0, mH1, b0, b1);
    fc_kernel<<<125, 256>>>(Wfc, bfc, out);
    softmax_kernel<<<32, 256>>>(out);
}

// round 10
// speedup vs baseline: 1.7157x; 1.0240x over previous
#include <cuda_runtime.h>
#include <cuda.h>
#include <cuda_fp16.h>
#include <cuda_fp8.h>

// 2-layer LSTM LM, B=32,S=512,H=1024,V=32000.
// fp8 weights resident in smem, fp8 activations via TMA, fp8 mma.sync.m16n8k32,
// per-CTA release flags, 4-deep TMA chunk pipeline, K-phase critical-path split.
#define B_   32
#define S_   512
#define H_   1024
#define V_   32000
#define GPL  64
#define HSLOT 32768

__device__ unsigned char g_W0[(size_t)4096 * 2048];       // fp8 e4m3 x16, [r][k]
__device__ unsigned char g_W1[(size_t)4096 * 2048];
__device__ unsigned char g_emb[(size_t)S_ * HSLOT];       // fp8 x64, [t*32+b][k]
__device__ unsigned char g_h0[(size_t)(S_ + 1) * HSLOT];  // fp8 x64
__device__ unsigned char g_h1[(size_t)(S_ + 1) * HSLOT];
__device__ unsigned g_flags0[GPL];
__device__ unsigned g_flags1[GPL];

struct Sm {
    unsigned char A[64][2064];       // 132096 B resident fp8 weights (stride 2064)
    unsigned char Bt[4][8192];       //  32768 B: 4 chunk buffers (2 SW128 boxes each)
    float         z[4][16][36];      //   9216 B gate staging
    unsigned char hst[32][16];       //    512 B h staging (coalesced store)
    unsigned long long mbar[4];
};                                   // 174624 B -> 1 CTA/SM

// ------------------------------ helpers -------------------------------------
__device__ __forceinline__ unsigned smem_u32(const void* p) {
    return (unsigned)__cvta_generic_to_shared(p);
}
__device__ __forceinline__ void cp16(void* dst, const void* src) {
    unsigned d = smem_u32(dst);
    asm volatile("cp.async.cg.shared.global [%0], [%1], 16;\n" :: "r"(d), "l"(src) : "memory");
}
__device__ __forceinline__ unsigned ld_acq(const unsigned* p) {
    unsigned v;
    asm volatile("ld.acquire.gpu.global.u32 %0, [%1];" : "=r"(v) : "l"(p) : "memory");
    return v;
}
__device__ __forceinline__ void st_rel(unsigned* p, unsigned v) {
    asm volatile("st.release.gpu.global.u32 [%0], %1;" :: "l"(p), "r"(v) : "memory");
}
__device__ __forceinline__ void mbar_init(unsigned a, unsigned c) {
    asm volatile("mbarrier.init.shared.b64 [%0], %1;" :: "r"(a), "r"(c) : "memory");
}
__device__ __forceinline__ void mbar_expect(unsigned a, unsigned bytes) {
    asm volatile("mbarrier.arrive.expect_tx.shared.b64 _, [%0], %1;" :: "r"(a), "r"(bytes) : "memory");
}
__device__ __forceinline__ void mbar_wait(unsigned a, unsigned ph) {
    asm volatile(
        "{\n\t.reg .pred P;\n"
        "W%=:\n\t"
        "mbarrier.try_wait.parity.acquire.cta.shared::cta.b64 P, [%0], %1, 0x989680;\n\t"
        "@!P bra W%=;\n\t}"
        :: "r"(a), "r"(ph) : "memory");
}
__device__ __forceinline__ void tma2d(unsigned dst, const CUtensorMap* m, int x, int y,
                                      unsigned mb) {
    asm volatile(
        "cp.async.bulk.tensor.2d.shared::cta.global.tile.mbarrier::complete_tx::bytes "
        "[%0], [%1, {%2, %3}], [%4];"
        :: "r"(dst), "l"(m), "r"(x), "r"(y), "r"(mb) : "memory");
}

// ------------------------------- prep ---------------------------------------
__global__ void prep_weights(const float* __restrict__ Wx, const float* __restrict__ Wh,
                             int layer) {
    unsigned char* __restrict__ W = layer ? g_W1 : g_W0;
    const size_t n = (size_t)4096 * 2048;
    for (size_t idx = (size_t)blockIdx.x * blockDim.x + threadIdx.x; idx < n;
         idx += (size_t)gridDim.x * blockDim.x) {
        int r = (int)(idx >> 11);
        int k = (int)(idx & 2047);
        int cgp = r >> 6, rem = r & 63;
        int gate = rem >> 4, uu = rem & 15;
        int j = gate * H_ + cgp * 16 + uu;
        float v = (k < H_) ? Wx[(size_t)k * 4096 + j]
                           : Wh[(size_t)(k - H_) * 4096 + j];
        W[idx] = (unsigned char)__nv_cvt_float_to_fp8(v * 16.f, __NV_SATFINITE, __NV_E4M3);
    }
}

__global__ void prep_embed(const int* __restrict__ x, const float* __restrict__ emb) {
    const size_t n = (size_t)S_ * HSLOT;
    for (size_t idx = (size_t)blockIdx.x * blockDim.x + threadIdx.x; idx < n;
         idx += (size_t)gridDim.x * blockDim.x) {
        int t   = (int)(idx >> 15);
        int rem = (int)(idx & 32767);
        int b   = rem >> 10;
        int k   = rem & 1023;
        float v = emb[(size_t)x[b * S_ + t] * H_ + k];
        g_emb[idx] = (unsigned char)__nv_cvt_float_to_fp8(v * 64.f, __NV_SATFINITE, __NV_E4M3);
    }
}

__global__ void prep_init() {
    for (int i = blockIdx.x * blockDim.x + threadIdx.x; i < HSLOT;
         i += gridDim.x * blockDim.x) {
        g_h0[i] = 0;
        g_h1[i] = 0;
    }
    if (blockIdx.x == 0 && threadIdx.x < GPL) {
        g_flags0[threadIdx.x] = 0u;
        g_flags1[threadIdx.x] = 0u;
    }
}

// --------------------------- persistent LSTM --------------------------------
__global__ void __launch_bounds__(256, 1)
lstm_persistent(const __grid_constant__ CUtensorMap mE,
                const __grid_constant__ CUtensorMap mH0,
                const __grid_constant__ CUtensorMap mH1,
                const float* __restrict__ bias0, const float* __restrict__ bias1) {
    extern __shared__ __align__(1024) char smem_raw[];
    Sm* S = reinterpret_cast<Sm*>(smem_raw);

    const int tid  = threadIdx.x;
    const int lane = tid & 31;
    const int w    = tid >> 5;
    const int g    = w >> 1;                 // gate 0..3
    const int nh   = w & 1;                  // batch half
    const bool l1  = (blockIdx.x >= GPL);
    const int cg   = l1 ? (blockIdx.x - GPL) : blockIdx.x;

    const unsigned char* __restrict__ Wg = (l1 ? g_W1 : g_W0) + (size_t)cg * 64 * 2048;
    const float* __restrict__ bias = l1 ? bias1 : bias0;
    unsigned char* hout = l1 ? g_h1 : g_h0;
    unsigned* myFlag = (l1 ? g_flags1 : g_flags0) + cg;

    // ---- resident fp8 weights (once) ----
    #pragma unroll
    for (int m = 0; m < 32; ++m) {
        int u   = tid + (m << 8);             // 0..8191 16B units
        int row = u >> 7;                     // 128 units per row
        int off = (u & 127) << 4;
        cp16(&S->A[row][off], Wg + (size_t)row * 2048 + off);
    }
    asm volatile("cp.async.commit_group;\ncp.async.wait_group 0;\n" ::: "memory");

    const unsigned mbAddr = smem_u32(&S->mbar[0]);
    const unsigned btAddr = smem_u32(&S->Bt[0][0]);
    if (tid == 0) {
        #pragma unroll
        for (int i = 0; i < 4; ++i) mbar_init(mbAddr + i * 8, 1);
    }
    asm volatile("fence.proxy.async.shared::cta;" ::: "memory");
    __syncthreads();

    // ---- A ldmatrix addressing (fp8 m16n8k32 fragments, natural k order) ----
    const unsigned aBase = smem_u32(
        &S->A[g * 16 + ((lane >> 3) & 1) * 8 + (lane & 7)][(lane >> 4) * 16]);
    // ---- B (activations, SW128 boxes [32 rows][128 cols]) ----
    const int b_row = nh * 16 + ((lane >> 4) & 1) * 8 + (lane & 7);
    const unsigned k16  = (lane >> 3) & 1;
    const unsigned xorv = (unsigned)(b_row & 7);
    const unsigned rowOff = (unsigned)b_row * 128;

    // ---- cell ownership ----
    const int u_loc = tid >> 4;
    const int u_g   = cg * 16 + u_loc;
    const int bb    = (tid & 15) << 1;
    const float bi  = bias[u_g];
    const float bf_ = bias[H_ + u_g];
    const float bg_ = bias[2 * H_ + u_g];
    const float bo_ = bias[3 * H_ + u_g];
    float c_st[2] = {0.f, 0.f};

    unsigned pc = 0;                          // phase counter (mbar parity)

    for (int t = 0; t < S_; ++t) {
        float acc[2][4] = {{0.f, 0.f, 0.f, 0.f}, {0.f, 0.f, 0.f, 0.f}};

        #pragma unroll
        for (int ph = 0; ph < 2; ++ph) {
            // ---- acquire producers (64 threads poll per-CTA flags) ----
            if (tid < GPL) {
                if (!l1) {
                    if (ph == 1) {
                        const unsigned tgt = (unsigned)t;
                        while (ld_acq(&g_flags0[tid]) < tgt) __nanosleep(32);
                    }
                } else {
                    if (ph == 0) {
                        const unsigned tgt = (unsigned)t;
                        while (ld_acq(&g_flags1[tid]) < tgt) __nanosleep(32);
                    } else {
                        const unsigned tgt = (unsigned)(t + 1);
                        while (ld_acq(&g_flags0[tid]) < tgt) __nanosleep(32);
                    }
                }
            }
            __syncthreads();

            // chunk ranges: l0 ph0 -> 0..3 (emb[t]), ph1 -> 4..7 (h0[t])
            //               l1 ph0 -> 4..7 (h1[t]), ph1 -> 0..3 (h0[t+1])
            const int cstart = l1 ? (ph ? 0 : 4) : (ph ? 4 : 0);

            if (tid == 0) {
                #pragma unroll
                for (int i = 0; i < 4; ++i) {
                    const int cc = cstart + i;
                    const unsigned mb = mbAddr + i * 8;
                    mbar_expect(mb, 8192u);
                    const CUtensorMap* m;
                    int x, y;
                    if (cc < 4) { m = l1 ? &mH0 : &mE;  y = (l1 ? (t + 1) : t) * 32; x = cc * 256; }
                    else        { m = l1 ? &mH1 : &mH0; y = t * 32;                  x = (cc - 4) * 256; }
                    const unsigned d = btAddr + i * 8192;
                    tma2d(d, m, x, y, mb);
                    tma2d(d + 4096, m, x + 128, y, mb);
                }
            }

            const unsigned par = pc & 1;
            #pragma unroll
            for (int i = 0; i < 4; ++i) {
                mbar_wait(mbAddr + i * 8, par);
                const int cc = cstart + i;
                const unsigned aA   = aBase + cc * 256;
                const unsigned bufB = btAddr + i * 8192 + rowOff;
                #pragma unroll
                for (int p = 0; p < 8; ++p) {
                    unsigned a0, a1, a2, a3;
                    asm volatile("ldmatrix.sync.aligned.m8n8.x4.shared.b16 {%0,%1,%2,%3}, [%4];\n"
                                 : "=r"(a0), "=r"(a1), "=r"(a2), "=r"(a3)
                                 : "r"(aA + p * 32));
                    const unsigned tt = 2u * p + k16;
                    const unsigned bA = bufB + (tt >> 3) * 4096 + ((tt & 7) ^ xorv) * 16;
                    unsigned b0, b1, b2, b3;
                    asm volatile("ldmatrix.sync.aligned.m8n8.x4.shared.b16 {%0,%1,%2,%3}, [%4];\n"
                                 : "=r"(b0), "=r"(b1), "=r"(b2), "=r"(b3)
                                 : "r"(bA));
                    asm volatile("mma.sync.aligned.m16n8k32.row.col.f32.e4m3.e4m3.f32 "
                                 "{%0,%1,%2,%3}, {%4,%5,%6,%7}, {%8,%9}, {%0,%1,%2,%3};\n"
                                 : "+f"(acc[0][0]), "+f"(acc[0][1]), "+f"(acc[0][2]), "+f"(acc[0][3])
                                 : "r"(a0), "r"(a1), "r"(a2), "r"(a3), "r"(b0), "r"(b1));
                    asm volatile("mma.sync.aligned.m16n8k32.row.col.f32.e4m3.e4m3.f32 "
                                 "{%0,%1,%2,%3}, {%4,%5,%6,%7}, {%8,%9}, {%0,%1,%2,%3};\n"
                                 : "+f"(acc[1][0]), "+f"(acc[1][1]), "+f"(acc[1][2]), "+f"(acc[1][3])
                                 : "r"(a0), "r"(a1), "r"(a2), "r"(a3), "r"(b2), "r"(b3));
                }
            }
            pc++;
        }

        // ---- stage z ----
        {
            const int r  = lane >> 2;
            const int cb = nh * 16 + ((lane & 3) << 1);
            #pragma unroll
            for (int nt = 0; nt < 2; ++nt) {
                S->z[g][r][cb + nt * 8]         = acc[nt][0];
                S->z[g][r][cb + nt * 8 + 1]     = acc[nt][1];
                S->z[g][r + 8][cb + nt * 8]     = acc[nt][2];
                S->z[g][r + 8][cb + nt * 8 + 1] = acc[nt][3];
            }
        }
        __syncthreads();

        // ---- LSTM cell (fp32; 1/1024 undoes the x16 weight, x64 act scales) ----
        #pragma unroll
        for (int j = 0; j < 2; ++j) {
            const int b = bb + j;
            float zi = S->z[0][u_loc][b] * 0.0009765625f + bi;
            float zf = S->z[1][u_loc][b] * 0.0009765625f + bf_;
            float zg = S->z[2][u_loc][b] * 0.0009765625f + bg_;
            float zo = S->z[3][u_loc][b] * 0.0009765625f + bo_;
            float ig = 1.f / (1.f + __expf(-zi));
            float fg = 1.f / (1.f + __expf(-zf));
            float og = 1.f / (1.f + __expf(-zo));
            float gc = tanhf(zg);
            c_st[j] = fg * c_st[j] + ig * gc;
            float h = og * tanhf(c_st[j]);
            S->hst[b][u_loc] =
                (unsigned char)__nv_cvt_float_to_fp8(h * 64.f, __NV_SATFINITE, __NV_E4M3);
        }
        __syncthreads();

        // ---- coalesced h store (32 x STG.128) + release ----
        if (tid < 32) {
            unsigned char* dst = hout + (size_t)(t + 1) * HSLOT + tid * H_ + cg * 16;
            *reinterpret_cast<uint4*>(dst) = *reinterpret_cast<const uint4*>(&S->hst[tid][0]);
        }
        __threadfence();
        __syncthreads();
        if (tid == 0) st_rel(myFlag, (unsigned)(t + 1));
    }
}

// ----------------------------- FC + softmax ---------------------------------
__global__ void fc_kernel(const float* __restrict__ Wfc, const float* __restrict__ bfc,
                          float* __restrict__ out) {
    __shared__ float hs[32][129];
    const int tidx = threadIdx.x;
    const int v = blockIdx.x * 256 + tidx;
    float acc[32];
    #pragma unroll
    for (int b = 0; b < 32; ++b) acc[b] = 0.f;

    const unsigned char* __restrict__ h1 = g_h1 + (size_t)S_ * HSLOT;
    for (int kt = 0; kt < 8; ++kt) {
        __syncthreads();
        for (int e = tidx; e < 32 * 128; e += 256) {
            int b = e >> 7, kk = e & 127;
            float hv = (float)(*reinterpret_cast<const __nv_fp8_e4m3*>(
                &h1[b * H_ + kt * 128 + kk]));
            hs[b][kk] = hv * 0.015625f;
        }
        __syncthreads();
        const float* w2 = Wfc + (size_t)(kt * 128) * V_ + v;
        #pragma unroll 4
        for (int kk = 0; kk < 128; ++kk) {
            float wv = w2[(size_t)kk * V_];
            #pragma unroll
            for (int b = 0; b < 32; ++b) acc[b] += hs[b][kk] * wv;
        }
    }
    const float bv = bfc[v];
    #pragma unroll
    for (int b = 0; b < 32; ++b) out[(size_t)b * V_ + v] = acc[b] + bv;
}

__global__ void softmax_kernel(float* __restrict__ out) {
    float* row = out + (size_t)blockIdx.x * V_;
    __shared__ float sd[32];
    const int tid = threadIdx.x;

    float m = -3.4e38f;
    for (int v = tid; v < V_; v += 256) m = fmaxf(m, row[v]);
    #pragma unroll
    for (int o = 16; o; o >>= 1) m = fmaxf(m, __shfl_xor_sync(0xffffffffu, m, o));
    if ((tid & 31) == 0) sd[tid >> 5] = m;
    __syncthreads();
    if (tid == 0) {
        float mm = sd[0];
        for (int i = 1; i < 8; ++i) mm = fmaxf(mm, sd[i]);
        sd[16] = mm;
    }
    __syncthreads();
    m = sd[16];

    float s = 0.f;
    for (int v = tid; v < V_; v += 256) s += expf(row[v] - m);
    #pragma unroll
    for (int o = 16; o; o >>= 1) s += __shfl_xor_sync(0xffffffffu, s, o);
    if ((tid & 31) == 0) sd[tid >> 5] = s;
    __syncthreads();
    if (tid == 0) {
        float ss = 0.f;
        for (int i = 0; i < 8; ++i) ss += sd[i];
        sd[17] = ss;
    }
    __syncthreads();
    const float inv = 1.f / sd[17];
    for (int v = tid; v < V_; v += 256) row[v] = expf(row[v] - m) * inv;
}

// ------------------------------- launch --------------------------------------
typedef CUresult (CUDAAPI *tmap_fn_t)(CUtensorMap*, CUtensorMapDataType, cuuint32_t,
                                      void*, const cuuint64_t*, const cuuint64_t*,
                                      const cuuint32_t*, const cuuint32_t*,
                                      CUtensorMapInterleave, CUtensorMapSwizzle,
                                      CUtensorMapL2promotion, CUtensorMapFloatOOBfill);

static void make_map(tmap_fn_t fn, CUtensorMap* m, void* base, unsigned long long rows) {
    cuuint64_t dims[2]    = {1024ull, rows};
    cuuint64_t strides[1] = {1024ull};
    cuuint32_t box[2]     = {128u, 32u};
    cuuint32_t es[2]      = {1u, 1u};
    fn(m, CU_TENSOR_MAP_DATA_TYPE_UINT8, 2, base, dims, strides, box, es,
       CU_TENSOR_MAP_INTERLEAVE_NONE, CU_TENSOR_MAP_SWIZZLE_128B,
       CU_TENSOR_MAP_L2_PROMOTION_L2_128B, CU_TENSOR_MAP_FLOAT_OOB_FILL_NONE);
}

extern "C" void kernel_launch(void* const* d_in, const int* in_sizes, int n_in,
                              void* d_out, int out_size) {
    const int*   x   = (const int*)d_in[0];
    const float* emb = (const float*)d_in[1];
    const float* Wx0 = (const float*)d_in[2];
    const float* Wh0 = (const float*)d_in[3];
    const float* b0  = (const float*)d_in[4];
    const float* Wx1 = (const float*)d_in[5];
    const float* Wh1 = (const float*)d_in[6];
    const float* b1  = (const float*)d_in[7];
    const float* Wfc = (const float*)d_in[8];
    const float* bfc = (const float*)d_in[9];
    float* out = (float*)d_out;

    tmap_fn_t fn = nullptr;
    cudaDriverEntryPointQueryResult st;
    cudaGetDriverEntryPointByVersion("cuTensorMapEncodeTiled", (void**)&fn, 12050,
                                     cudaEnableDefault, &st);
    void *pE = nullptr, *pH0 = nullptr, *pH1 = nullptr;
    cudaGetSymbolAddress(&pE, g_emb);
    cudaGetSymbolAddress(&pH0, g_h0);
    cudaGetSymbolAddress(&pH1, g_h1);
    CUtensorMap mE, mH0, mH1;
    make_map(fn, &mE, pE, (unsigned long long)S_ * 32ull);
    make_map(fn, &mH0, pH0, (unsigned long long)(S_ + 1) * 32ull);
    make_map(fn, &mH1, pH1, (unsigned long long)(S_ + 1) * 32ull);

    cudaFuncSetAttribute(lstm_persistent,
                         cudaFuncAttributeMaxDynamicSharedMemorySize, (int)sizeof(Sm));

    prep_weights<<<2048, 256>>>(Wx0, Wh0, 0);
    prep_weights<<<2048, 256>>>(Wx1, Wh1, 1);
    prep_embed<<<2048, 256>>>(x, emb);
    prep_init<<<64, 256>>>();
    lstm_persistent<<<128, 256, sizeof(Sm)>>>(mE, mH0, mH1, b0, b1);
    fc_kernel<<<125, 256>>>(Wfc, bfc, out);
    softmax_kernel<<<32, 256>>>(out);
}